// round 5
// baseline (speedup 1.0000x reference)
#include <cuda_runtime.h>
#include <math.h>

// Problem constants
#define M_TOK   65536      // B*T = 16*4096
#define DIM     128
#define KCODE   1024
#define BM      128        // tokens per block
#define BN      128        // codes per n-tile
#define NTILES  (KCODE/BN) // 8
#define GRID_MAIN (M_TOK/BM) // 512

// Output layout (floats): [z_q | similarity | ids | loss]
#define SIM_OFF  8388608ULL   // 16*4096*128
#define IDS_OFF  75497472ULL  // + 16*4096*1024
#define LOSS_OFF 75563008ULL  // + 65536

// Scratch (__device__ globals; no allocation allowed)
__device__ float g_nz[M_TOK];
__device__ float g_rz[M_TOK];
__device__ float g_ne[KCODE];
__device__ float g_re[KCODE];
__device__ float g_partial[GRID_MAIN];

// ---- packed f32x2 helpers (ptxas never auto-fuses; PTX only) ----
__device__ __forceinline__ unsigned long long pk2(float a, float b) {
    unsigned long long r;
    asm("mov.b64 %0, {%1,%2};" : "=l"(r) : "f"(a), "f"(b));
    return r;
}
__device__ __forceinline__ void upk2(unsigned long long v, float& a, float& b) {
    asm("mov.b64 {%0,%1}, %2;" : "=f"(a), "=f"(b) : "l"(v));
}
__device__ __forceinline__ void fma2(unsigned long long& c, unsigned long long a, unsigned long long b) {
    asm("fma.rn.f32x2 %0, %1, %2, %0;" : "+l"(c) : "l"(a), "l"(b));
}

// ---- row-wise squared norms + rsqrt (warp per row, D=128) ----
__global__ void row_norm_z(const float* __restrict__ x) {
    int row  = blockIdx.x * 8 + (threadIdx.x >> 5);
    int lane = threadIdx.x & 31;
    float4 v = reinterpret_cast<const float4*>(x)[(size_t)row * 32 + lane];
    float s = fmaf(v.x, v.x, fmaf(v.y, v.y, fmaf(v.z, v.z, v.w * v.w)));
#pragma unroll
    for (int m = 16; m; m >>= 1) s += __shfl_xor_sync(0xffffffffu, s, m);
    if (lane == 0) { g_nz[row] = s; g_rz[row] = rsqrtf(s); }
}
__global__ void row_norm_e(const float* __restrict__ x) {
    int row  = blockIdx.x * 8 + (threadIdx.x >> 5);
    int lane = threadIdx.x & 31;
    float4 v = reinterpret_cast<const float4*>(x)[(size_t)row * 32 + lane];
    float s = fmaf(v.x, v.x, fmaf(v.y, v.y, fmaf(v.z, v.z, v.w * v.w)));
#pragma unroll
    for (int m = 16; m; m >>= 1) s += __shfl_xor_sync(0xffffffffu, s, m);
    if (lane == 0) { g_ne[row] = s; g_re[row] = rsqrtf(s); }
}

// Transpose-load a [128 rows x 128 cols] fp32 tile into smem as [d][x] with
// XOR swizzle on the 16B unit index: element (d, r) lives at
//   d*128 + (((r>>2) ^ (d>>2)) << 2) + (r & 3)
// Stores: <=4-way conflicts (cheap, once per tile). Reads: conflict-free LDS.128.
__device__ __forceinline__ void load_tile_T(const float* __restrict__ S, float* __restrict__ dst,
                                            int warp, int lane) {
    const float4* S4 = reinterpret_cast<const float4*>(S);
#pragma unroll
    for (int it = 0; it < 16; ++it) {
        int r = warp * 16 + it;
        float4 v = S4[r * 32 + lane];
#pragma unroll
        for (int j = 0; j < 4; ++j) {
            int d = lane * 4 + j;
            float f = (j == 0) ? v.x : (j == 1) ? v.y : (j == 2) ? v.z : v.w;
            dst[d * 128 + ((((r >> 2) ^ (d >> 2)) & 31) << 2) + (r & 3)] = f;
        }
    }
}

__global__ __launch_bounds__(256, 1)
void vq_main(const float* __restrict__ Z, const float* __restrict__ E, float* __restrict__ out) {
    extern __shared__ float smem[];
    float* As    = smem;                    // 16384 floats (z tile, transposed+swizzled)
    float* Bs    = smem + BM * DIM;         // 16384 floats (E tile, transposed+swizzled)
    float* ne_sm = smem + 2 * BM * DIM;     // 1024
    float* re_sm = ne_sm + KCODE;           // 1024
    int*   ids_sm = (int*)(re_sm + KCODE);  // 128
    float* lt_sm  = (float*)(ids_sm + BM);  // 128

    const int tid  = threadIdx.x;
    const int lane = tid & 31;
    const int warp = tid >> 5;
    const int tx   = tid & 15;   // n-direction
    const int ty   = tid >> 4;   // m-direction
    const int m0   = blockIdx.x * BM;

    float* zq   = out;
    float* sim  = out + SIM_OFF;
    float* idsf = out + IDS_OFF;

    // Preload z tile (once) and full codebook norms into smem
    load_tile_T(Z + (size_t)m0 * DIM, As, warp, lane);
    for (int i = tid; i < KCODE; i += 256) { ne_sm[i] = g_ne[i]; re_sm[i] = g_re[i]; }

    float bestD[8];
    int   bestI[8];
#pragma unroll
    for (int i = 0; i < 8; i++) { bestD[i] = 3.4e38f; bestI[i] = 0; }

    __syncthreads();

    const float4*     As4 = reinterpret_cast<const float4*>(As);
    const ulonglong2* Bs2 = reinterpret_cast<const ulonglong2*>(Bs);

    for (int t = 0; t < NTILES; ++t) {
        if (t) __syncthreads();                      // prev tile reads done before overwrite
        load_tile_T(E + (size_t)t * BN * DIM, Bs, warp, lane);
        __syncthreads();

        unsigned long long acc[8][4];
#pragma unroll
        for (int i = 0; i < 8; i++)
#pragma unroll
            for (int j = 0; j < 4; j++) acc[i][j] = 0ULL;

        // 128-deep dot product, 8(m) x 8(n) per thread, packed f32x2 FMAs
#pragma unroll 4
        for (int d = 0; d < DIM; ++d) {
            int sw = d >> 2;
            float4     a0 = As4[d * 32 + (ty ^ sw)];
            float4     a1 = As4[d * 32 + ((ty + 16) ^ sw)];
            ulonglong2 b0 = Bs2[d * 32 + (tx ^ sw)];
            ulonglong2 b1 = Bs2[d * 32 + ((tx + 16) ^ sw)];
            unsigned long long av[8];
            av[0] = pk2(a0.x, a0.x); av[1] = pk2(a0.y, a0.y);
            av[2] = pk2(a0.z, a0.z); av[3] = pk2(a0.w, a0.w);
            av[4] = pk2(a1.x, a1.x); av[5] = pk2(a1.y, a1.y);
            av[6] = pk2(a1.z, a1.z); av[7] = pk2(a1.w, a1.w);
            unsigned long long bv[4] = { b0.x, b0.y, b1.x, b1.y };
#pragma unroll
            for (int i = 0; i < 8; i++)
#pragma unroll
                for (int j = 0; j < 4; j++) fma2(acc[i][j], av[i], bv[j]);
        }

        // Epilogue: dist/argmin + similarity write
        const int nb = t * BN;
        float ne0[4], ne1[4], re0[4], re1[4];
#pragma unroll
        for (int q = 0; q < 4; q++) {
            ne0[q] = ne_sm[nb + 4 * tx + q];      re0[q] = re_sm[nb + 4 * tx + q];
            ne1[q] = ne_sm[nb + 64 + 4 * tx + q]; re1[q] = re_sm[nb + 64 + 4 * tx + q];
        }
#pragma unroll
        for (int i = 0; i < 8; i++) {
            const int ml = (i < 4) ? (4 * ty + i) : (60 + 4 * ty + i);
            const size_t mg = (size_t)(m0 + ml);
            float pv0[4], pv1[4];
            upk2(acc[i][0], pv0[0], pv0[1]); upk2(acc[i][1], pv0[2], pv0[3]);
            upk2(acc[i][2], pv1[0], pv1[1]); upk2(acc[i][3], pv1[2], pv1[3]);
            const float nzi = g_nz[mg];
            const float rzi = g_rz[mg];
            // argmin update — reference association order: (-2*dot + nz) + ne;
            // strict '<' keeps the first (lowest) index, matching jnp.argmin ties.
#pragma unroll
            for (int q = 0; q < 4; q++) {
                float dd = (-2.f * pv0[q] + nzi) + ne0[q];
                if (dd < bestD[i]) { bestD[i] = dd; bestI[i] = nb + 4 * tx + q; }
            }
#pragma unroll
            for (int q = 0; q < 4; q++) {
                float dd = (-2.f * pv1[q] + nzi) + ne1[q];
                if (dd < bestD[i]) { bestD[i] = dd; bestI[i] = nb + 64 + 4 * tx + q; }
            }
            float4 s0 = make_float4(pv0[0] * rzi * re0[0], pv0[1] * rzi * re0[1],
                                    pv0[2] * rzi * re0[2], pv0[3] * rzi * re0[3]);
            float4 s1 = make_float4(pv1[0] * rzi * re1[0], pv1[1] * rzi * re1[1],
                                    pv1[2] * rzi * re1[2], pv1[3] * rzi * re1[3]);
            reinterpret_cast<float4*>(sim + mg * KCODE + nb + 4 * tx)[0]      = s0;
            reinterpret_cast<float4*>(sim + mg * KCODE + nb + 64 + 4 * tx)[0] = s1;
        }
    }

    // Reduce argmin across the 16 tx-lanes (lanes 0-15 / 16-31 independently)
#pragma unroll
    for (int i = 0; i < 8; i++) {
        float bd = bestD[i]; int bi = bestI[i];
#pragma unroll
        for (int msk = 1; msk < 16; msk <<= 1) {
            float od = __shfl_xor_sync(0xffffffffu, bd, msk);
            int   oi = __shfl_xor_sync(0xffffffffu, bi, msk);
            if (od < bd || (od == bd && oi < bi)) { bd = od; bi = oi; }
        }
        if (tx == 0) {
            const int ml = (i < 4) ? (4 * ty + i) : (60 + 4 * ty + i);
            ids_sm[ml] = bi;
            idsf[m0 + ml] = (float)bi;
            // ||z_e - z_q||^2 == dist_min exactly
            lt_sm[ml] = sqrtf(fmaxf(bd, 0.f));
        }
    }
    __syncthreads();

    // Gather z_q rows from the codebook (E is L2-resident)
    const float4* E4  = reinterpret_cast<const float4*>(E);
    float4*       ZQ4 = reinterpret_cast<float4*>(zq);
#pragma unroll
    for (int r = 0; r < 16; r++) {
        int ml = warp * 16 + r;
        int id = ids_sm[ml];
        ZQ4[(size_t)(m0 + ml) * 32 + lane] = E4[(size_t)id * 32 + lane];
    }

    // Deterministic per-block loss partial (fixed serial order)
    if (tid == 0) {
        float s = 0.f;
        for (int i = 0; i < BM; i++) s += lt_sm[i];
        g_partial[blockIdx.x] = s;
    }
}

// loss = loss_codebook + BETA*loss_commit = 1.25 * mean ||z_e - z_q||
__global__ void loss_final(float* __restrict__ out) {
    float s = 0.f;
    for (int i = 0; i < GRID_MAIN; i++) s += g_partial[i];
    out[LOSS_OFF] = 1.25f * (s * (1.f / 65536.f));
}

extern "C" void kernel_launch(void* const* d_in, const int* in_sizes, int n_in,
                              void* d_out, int out_size) {
    (void)in_sizes; (void)n_in; (void)out_size;
    const float* Z = (const float*)d_in[0];   // z_e            [65536, 128]
    const float* E = (const float*)d_in[1];   // vecs_embedding [1024, 128]
    float* out = (float*)d_out;

    const size_t smem_bytes = (size_t)(2 * BM * DIM + 2 * KCODE) * sizeof(float)
                            + BM * sizeof(int) + BM * sizeof(float);
    cudaFuncSetAttribute((const void*)vq_main,
                         cudaFuncAttributeMaxDynamicSharedMemorySize, (int)smem_bytes);

    row_norm_z<<<M_TOK / 8, 256>>>(Z);
    row_norm_e<<<KCODE / 8, 256>>>(E);
    vq_main<<<GRID_MAIN, 256, smem_bytes>>>(Z, E, out);
    loss_final<<<1, 1>>>(out);
}

// round 6
// speedup vs baseline: 1.0581x; 1.0581x over previous
#include <cuda_runtime.h>
#include <math.h>

// Problem constants
#define M_TOK   65536      // B*T = 16*4096
#define DIM     128
#define KCODE   1024
#define BM      128        // tokens per block
#define BN      128        // codes per n-tile
#define NTILES  (KCODE/BN) // 8
#define GRID_MAIN (M_TOK/BM) // 512

// Output layout (floats): [z_q | similarity | ids | loss]
#define SIM_OFF  8388608ULL   // 16*4096*128
#define IDS_OFF  75497472ULL  // + 16*4096*1024
#define LOSS_OFF 75563008ULL  // + 65536

// Scratch (__device__ globals; no allocation allowed)
__device__ float g_nz[M_TOK];
__device__ float g_rz[M_TOK];
__device__ float g_ne[KCODE];
__device__ float g_re[KCODE];
__device__ float g_partial[GRID_MAIN];

// ---- packed f32x2 helpers (ptxas never auto-fuses; PTX only) ----
__device__ __forceinline__ unsigned long long pk2(float a, float b) {
    unsigned long long r;
    asm("mov.b64 %0, {%1,%2};" : "=l"(r) : "f"(a), "f"(b));
    return r;
}
__device__ __forceinline__ void upk2(unsigned long long v, float& a, float& b) {
    asm("mov.b64 {%0,%1}, %2;" : "=f"(a), "=f"(b) : "l"(v));
}
__device__ __forceinline__ void fma2(unsigned long long& c, unsigned long long a, unsigned long long b) {
    asm("fma.rn.f32x2 %0, %1, %2, %0;" : "+l"(c) : "l"(a), "l"(b));
}

// ---- row-wise squared norms + rsqrt (warp per row, D=128) ----
__global__ void row_norm_z(const float* __restrict__ x) {
    int row  = blockIdx.x * 8 + (threadIdx.x >> 5);
    int lane = threadIdx.x & 31;
    float4 v = reinterpret_cast<const float4*>(x)[(size_t)row * 32 + lane];
    float s = fmaf(v.x, v.x, fmaf(v.y, v.y, fmaf(v.z, v.z, v.w * v.w)));
#pragma unroll
    for (int m = 16; m; m >>= 1) s += __shfl_xor_sync(0xffffffffu, s, m);
    if (lane == 0) { g_nz[row] = s; g_rz[row] = rsqrtf(s); }
}
__global__ void row_norm_e(const float* __restrict__ x) {
    int row  = blockIdx.x * 8 + (threadIdx.x >> 5);
    int lane = threadIdx.x & 31;
    float4 v = reinterpret_cast<const float4*>(x)[(size_t)row * 32 + lane];
    float s = fmaf(v.x, v.x, fmaf(v.y, v.y, fmaf(v.z, v.z, v.w * v.w)));
#pragma unroll
    for (int m = 16; m; m >>= 1) s += __shfl_xor_sync(0xffffffffu, s, m);
    if (lane == 0) { g_ne[row] = s; g_re[row] = rsqrtf(s); }
}

// Transpose-load a [128 rows x 128 cols] fp32 tile into smem as [d][x] with
// XOR swizzle on the 16B unit index: element (d, r) lives at
//   d*128 + (((r>>2) ^ (d>>2)) << 2) + (r & 3)
// Stores: <=4-way conflicts (cheap, once per tile). Reads: conflict-free LDS.128.
__device__ __forceinline__ void load_tile_T(const float* __restrict__ S, float* __restrict__ dst,
                                            int warp, int lane) {
    const float4* S4 = reinterpret_cast<const float4*>(S);
#pragma unroll
    for (int it = 0; it < 16; ++it) {
        int r = warp * 16 + it;
        float4 v = S4[r * 32 + lane];
#pragma unroll
        for (int j = 0; j < 4; ++j) {
            int d = lane * 4 + j;
            float f = (j == 0) ? v.x : (j == 1) ? v.y : (j == 2) ? v.z : v.w;
            dst[d * 128 + ((((r >> 2) ^ (d >> 2)) & 31) << 2) + (r & 3)] = f;
        }
    }
}

__global__ __launch_bounds__(256, 1)
void vq_main(const float* __restrict__ Z, const float* __restrict__ E, float* __restrict__ out) {
    extern __shared__ float smem[];
    float* As    = smem;                    // 16384 floats (z tile, transposed+swizzled)
    float* Bs    = smem + BM * DIM;         // 16384 floats (E tile, transposed+swizzled)
    float* ne_sm = smem + 2 * BM * DIM;     // 1024
    float* re_sm = ne_sm + KCODE;           // 1024
    int*   ids_sm = (int*)(re_sm + KCODE);  // 128
    float* lt_sm  = (float*)(ids_sm + BM);  // 128

    const int tid  = threadIdx.x;
    const int lane = tid & 31;
    const int warp = tid >> 5;
    const int tx   = tid & 15;   // n-direction
    const int ty   = tid >> 4;   // m-direction
    const int m0   = blockIdx.x * BM;

    float* zq   = out;
    float* sim  = out + SIM_OFF;
    float* idsf = out + IDS_OFF;

    // Preload z tile (once) and full codebook norms into smem
    load_tile_T(Z + (size_t)m0 * DIM, As, warp, lane);
    for (int i = tid; i < KCODE; i += 256) { ne_sm[i] = g_ne[i]; re_sm[i] = g_re[i]; }

    float bestD[8];
    int   bestI[8];
#pragma unroll
    for (int i = 0; i < 8; i++) { bestD[i] = 3.4e38f; bestI[i] = 0; }

    __syncthreads();

    const float4*     As4 = reinterpret_cast<const float4*>(As);
    const ulonglong2* Bs2 = reinterpret_cast<const ulonglong2*>(Bs);

    for (int t = 0; t < NTILES; ++t) {
        if (t) __syncthreads();                      // prev tile reads done before overwrite
        load_tile_T(E + (size_t)t * BN * DIM, Bs, warp, lane);
        __syncthreads();

        unsigned long long acc[8][4];
#pragma unroll
        for (int i = 0; i < 8; i++)
#pragma unroll
            for (int j = 0; j < 4; j++) acc[i][j] = 0ULL;

        // 128-deep dot product, 8(m) x 8(n) per thread, packed f32x2 FMAs
#pragma unroll 4
        for (int d = 0; d < DIM; ++d) {
            int sw = d >> 2;
            float4     a0 = As4[d * 32 + (ty ^ sw)];
            float4     a1 = As4[d * 32 + ((ty + 16) ^ sw)];
            ulonglong2 b0 = Bs2[d * 32 + (tx ^ sw)];
            ulonglong2 b1 = Bs2[d * 32 + ((tx + 16) ^ sw)];
            unsigned long long av[8];
            av[0] = pk2(a0.x, a0.x); av[1] = pk2(a0.y, a0.y);
            av[2] = pk2(a0.z, a0.z); av[3] = pk2(a0.w, a0.w);
            av[4] = pk2(a1.x, a1.x); av[5] = pk2(a1.y, a1.y);
            av[6] = pk2(a1.z, a1.z); av[7] = pk2(a1.w, a1.w);
            unsigned long long bv[4] = { b0.x, b0.y, b1.x, b1.y };
#pragma unroll
            for (int i = 0; i < 8; i++)
#pragma unroll
                for (int j = 0; j < 4; j++) fma2(acc[i][j], av[i], bv[j]);
        }

        // Epilogue: dist/argmin + similarity write
        const int nb = t * BN;
        float ne0[4], ne1[4], re0[4], re1[4];
#pragma unroll
        for (int q = 0; q < 4; q++) {
            ne0[q] = ne_sm[nb + 4 * tx + q];      re0[q] = re_sm[nb + 4 * tx + q];
            ne1[q] = ne_sm[nb + 64 + 4 * tx + q]; re1[q] = re_sm[nb + 64 + 4 * tx + q];
        }
#pragma unroll
        for (int i = 0; i < 8; i++) {
            const int ml = (i < 4) ? (4 * ty + i) : (60 + 4 * ty + i);
            const size_t mg = (size_t)(m0 + ml);
            float pv0[4], pv1[4];
            upk2(acc[i][0], pv0[0], pv0[1]); upk2(acc[i][1], pv0[2], pv0[3]);
            upk2(acc[i][2], pv1[0], pv1[1]); upk2(acc[i][3], pv1[2], pv1[3]);
            const float nzi = g_nz[mg];
            const float rzi = g_rz[mg];
            // argmin update — reference association order: (-2*dot + nz) + ne;
            // strict '<' keeps the first (lowest) index, matching jnp.argmin ties.
#pragma unroll
            for (int q = 0; q < 4; q++) {
                float dd = (-2.f * pv0[q] + nzi) + ne0[q];
                if (dd < bestD[i]) { bestD[i] = dd; bestI[i] = nb + 4 * tx + q; }
            }
#pragma unroll
            for (int q = 0; q < 4; q++) {
                float dd = (-2.f * pv1[q] + nzi) + ne1[q];
                if (dd < bestD[i]) { bestD[i] = dd; bestI[i] = nb + 64 + 4 * tx + q; }
            }
            float4 s0 = make_float4(pv0[0] * rzi * re0[0], pv0[1] * rzi * re0[1],
                                    pv0[2] * rzi * re0[2], pv0[3] * rzi * re0[3]);
            float4 s1 = make_float4(pv1[0] * rzi * re1[0], pv1[1] * rzi * re1[1],
                                    pv1[2] * rzi * re1[2], pv1[3] * rzi * re1[3]);
            reinterpret_cast<float4*>(sim + mg * KCODE + nb + 4 * tx)[0]      = s0;
            reinterpret_cast<float4*>(sim + mg * KCODE + nb + 64 + 4 * tx)[0] = s1;
        }
    }

    // Reduce argmin across the 16 tx-lanes (lanes 0-15 / 16-31 independently)
#pragma unroll
    for (int i = 0; i < 8; i++) {
        float bd = bestD[i]; int bi = bestI[i];
#pragma unroll
        for (int msk = 1; msk < 16; msk <<= 1) {
            float od = __shfl_xor_sync(0xffffffffu, bd, msk);
            int   oi = __shfl_xor_sync(0xffffffffu, bi, msk);
            if (od < bd || (od == bd && oi < bi)) { bd = od; bi = oi; }
        }
        if (tx == 0) {
            const int ml = (i < 4) ? (4 * ty + i) : (60 + 4 * ty + i);
            ids_sm[ml] = bi;
            idsf[m0 + ml] = (float)bi;
            // ||z_e - z_q||^2 == dist_min exactly
            lt_sm[ml] = sqrtf(fmaxf(bd, 0.f));
        }
    }
    __syncthreads();

    // Gather z_q rows from the codebook (E is L2-resident)
    const float4* E4  = reinterpret_cast<const float4*>(E);
    float4*       ZQ4 = reinterpret_cast<float4*>(zq);
#pragma unroll
    for (int r = 0; r < 16; r++) {
        int ml = warp * 16 + r;
        int id = ids_sm[ml];
        ZQ4[(size_t)(m0 + ml) * 32 + lane] = E4[(size_t)id * 32 + lane];
    }

    // Deterministic per-block loss partial (fixed serial order)
    if (tid == 0) {
        float s = 0.f;
        for (int i = 0; i < BM; i++) s += lt_sm[i];
        g_partial[blockIdx.x] = s;
    }
}

// loss = loss_codebook + BETA*loss_commit = 1.25 * mean ||z_e - z_q||
__global__ void loss_final(float* __restrict__ out) {
    float s = 0.f;
    for (int i = 0; i < GRID_MAIN; i++) s += g_partial[i];
    out[LOSS_OFF] = 1.25f * (s * (1.f / 65536.f));
}

extern "C" void kernel_launch(void* const* d_in, const int* in_sizes, int n_in,
                              void* d_out, int out_size) {
    (void)in_sizes; (void)n_in; (void)out_size;
    const float* Z = (const float*)d_in[0];   // z_e            [65536, 128]
    const float* E = (const float*)d_in[1];   // vecs_embedding [1024, 128]
    float* out = (float*)d_out;

    const size_t smem_bytes = (size_t)(2 * BM * DIM + 2 * KCODE) * sizeof(float)
                            + BM * sizeof(int) + BM * sizeof(float);
    cudaFuncSetAttribute((const void*)vq_main,
                         cudaFuncAttributeMaxDynamicSharedMemorySize, (int)smem_bytes);

    row_norm_z<<<M_TOK / 8, 256>>>(Z);
    row_norm_e<<<KCODE / 8, 256>>>(E);
    vq_main<<<GRID_MAIN, 256, smem_bytes>>>(Z, E, out);
    loss_final<<<1, 1>>>(out);
}

// round 8
// speedup vs baseline: 1.2092x; 1.1428x over previous
#include <cuda_runtime.h>
#include <cuda_bf16.h>
#include <math.h>
#include <stdint.h>

// ---------------- problem constants ----------------
#define M_TOK   65536
#define KCODE   1024
#define BM      128
#define BN      64            // codes per chunk
#define NCHUNK  16
#define GRID_MAIN 512

// Output layout (floats): [z_q | similarity | ids | loss]
#define SIM_OFF   8388608ULL
#define IDSG_OFF  75497472ULL
#define LOSS_OFF  75563008ULL

// ---------------- smem layout (byte offsets) ----------------
#define A_LVL      32768          // one A level: 128 rows x 256B
#define B_OFF      98304          // A = 3 levels = 98304
#define B_BUF      49152          // one B buffer: 3 levels x 16384
#define B_LVL      16384
#define NE_OFF     196608
#define RE_OFF     200704
#define NZ_OFF     204800
#define RZ_OFF     205312
#define IDS_SM     205824
#define LT_SM      206336
#define RED_OFF    206848         // 2048B dist + 2048B idx
#define SMEM_BYTES 210944

// ---------------- device scratch ----------------
__device__ __align__(16) __nv_bfloat16 g_Eb[KCODE * 384]; // per row: [e1|e2|e3] x128
__device__ float g_ne[KCODE];
__device__ float g_re[KCODE];
__device__ float g_partial[GRID_MAIN];

// ---------------- PTX helpers (baseline ISA only — no 'a' features) --------
__device__ __forceinline__ uint32_t smem_u32(const void* p) {
    uint32_t a;
    asm("{ .reg .u64 t; cvta.to.shared.u64 t, %1; cvt.u32.u64 %0, t; }" : "=r"(a) : "l"(p));
    return a;
}
__device__ __forceinline__ void cp16(uint32_t saddr, const void* g) {
    asm volatile("cp.async.cg.shared.global [%0], [%1], 16;" :: "r"(saddr), "l"(g));
}
__device__ __forceinline__ void cp_commit() { asm volatile("cp.async.commit_group;" ::: "memory"); }
template <int N>
__device__ __forceinline__ void cp_wait() { asm volatile("cp.async.wait_group %0;" :: "n"(N) : "memory"); }

__device__ __forceinline__ void ldsm_x4(uint32_t& r0, uint32_t& r1, uint32_t& r2, uint32_t& r3,
                                        uint32_t addr) {
    asm volatile("ldmatrix.sync.aligned.m8n8.x4.shared.b16 {%0,%1,%2,%3}, [%4];"
                 : "=r"(r0), "=r"(r1), "=r"(r2), "=r"(r3) : "r"(addr));
}
__device__ __forceinline__ void mma_bf16(float* c, const uint32_t* a, const uint32_t* b) {
    asm volatile("mma.sync.aligned.m16n8k16.row.col.f32.bf16.bf16.f32 "
                 "{%0,%1,%2,%3}, {%4,%5,%6,%7}, {%8,%9}, {%0,%1,%2,%3};"
                 : "+f"(c[0]), "+f"(c[1]), "+f"(c[2]), "+f"(c[3])
                 : "r"(a[0]), "r"(a[1]), "r"(a[2]), "r"(a[3]), "r"(b[0]), "r"(b[1]));
}

// ---------------- 3-level bf16 split of a float pair, packed b32 per level --
__device__ __forceinline__ void split_pack(float a, float b,
                                           uint32_t& o1, uint32_t& o2, uint32_t& o3) {
    __nv_bfloat16 a1 = __float2bfloat16(a);
    float ar = a - __bfloat162float(a1);
    __nv_bfloat16 a2 = __float2bfloat16(ar);
    float ar2 = ar - __bfloat162float(a2);
    __nv_bfloat16 a3 = __float2bfloat16(ar2);
    __nv_bfloat16 b1 = __float2bfloat16(b);
    float br = b - __bfloat162float(b1);
    __nv_bfloat16 b2 = __float2bfloat16(br);
    float br2 = br - __bfloat162float(b2);
    __nv_bfloat16 b3 = __float2bfloat16(br2);
    __nv_bfloat162 p1 = __halves2bfloat162(a1, b1);
    __nv_bfloat162 p2 = __halves2bfloat162(a2, b2);
    __nv_bfloat162 p3 = __halves2bfloat162(a3, b3);
    o1 = *reinterpret_cast<uint32_t*>(&p1);
    o2 = *reinterpret_cast<uint32_t*>(&p2);
    o3 = *reinterpret_cast<uint32_t*>(&p3);
}

// ---------------- codebook prep: split + norms (warp per row) ---------------
__global__ void prep_e(const float* __restrict__ E) {
    int row  = blockIdx.x * 8 + (threadIdx.x >> 5);
    int lane = threadIdx.x & 31;
    float4 v = reinterpret_cast<const float4*>(E)[(size_t)row * 32 + lane];
    float s = fmaf(v.x, v.x, fmaf(v.y, v.y, fmaf(v.z, v.z, v.w * v.w)));
#pragma unroll
    for (int m = 16; m; m >>= 1) s += __shfl_xor_sync(0xffffffffu, s, m);
    if (lane == 0) { g_ne[row] = s; g_re[row] = rsqrtf(s); }
    uint32_t u1a, u2a, u3a, u1b, u2b, u3b;
    split_pack(v.x, v.y, u1a, u2a, u3a);
    split_pack(v.z, v.w, u1b, u2b, u3b);
    uint32_t* dst = reinterpret_cast<uint32_t*>(g_Eb + (size_t)row * 384);
    dst[lane * 2]       = u1a;  dst[lane * 2 + 1]       = u1b;   // level 1
    dst[64 + lane * 2]  = u2a;  dst[64 + lane * 2 + 1]  = u2b;   // level 2
    dst[128 + lane * 2] = u3a;  dst[128 + lane * 2 + 1] = u3b;   // level 3
}

// ---------------- B chunk loader: 64 codes x 3 levels = 48KB -----------------
__device__ __forceinline__ void load_B(uint32_t sbuf, int nb, int tid) {
#pragma unroll
    for (int i = 0; i < 12; ++i) {
        int idx = tid + 256 * i;          // 0..3071
        int lvl = idx >> 10;
        int rem = idx & 1023;
        int r   = rem >> 4;               // local code 0..63
        int j   = rem & 15;               // 16B column unit
        cp16(sbuf + lvl * B_LVL + (uint32_t)r * 256u
                  + (((uint32_t)(j ^ (r & 7))) << 4),
             g_Eb + (size_t)(nb + r) * 384 + lvl * 128 + j * 8);
    }
}

// ---------------- main fused kernel ----------------
__global__ __launch_bounds__(256, 1)
void vq_main(const float* __restrict__ Z, const float* __restrict__ E,
             float* __restrict__ out) {
    extern __shared__ char sb[];
    const uint32_t sbase = smem_u32(sb);

    const int tid  = threadIdx.x;
    const int lane = tid & 31;
    const int warp = tid >> 5;
    const int wy   = warp >> 2;      // m half (0,1)
    const int wx   = warp & 3;       // n quarter (0..3)
    const int qrow = lane >> 2;
    const int qcol = lane & 3;
    const int m0   = blockIdx.x * BM;

    float* ne_sm = (float*)(sb + NE_OFF);
    float* re_sm = (float*)(sb + RE_OFF);
    float* nz_sm = (float*)(sb + NZ_OFF);
    float* rz_sm = (float*)(sb + RZ_OFF);
    int*   ids_sm = (int*)(sb + IDS_SM);
    float* lt_sm  = (float*)(sb + LT_SM);
    float* redD   = (float*)(sb + RED_OFF);
    int*   redI   = (int*)(sb + RED_OFF + 2048);

    float* zq   = out;
    float* sim  = out + SIM_OFF;
    float* idsf = out + IDSG_OFF;

    // kick off B chunks 0,1 (independent of A prologue)
    load_B(sbase + B_OFF, 0, tid);          cp_commit();
    load_B(sbase + B_OFF + B_BUF, 64, tid); cp_commit();

    // codebook norms into smem
    for (int i = tid; i < KCODE; i += 256) { ne_sm[i] = g_ne[i]; re_sm[i] = g_re[i]; }

    // A prologue: thread = (row, k-half); exact fp32 norm + 3-level bf16 split
    {
        const int row = tid >> 1, kh = tid & 1;
        const float4* Zr = reinterpret_cast<const float4*>(
            Z + (size_t)(m0 + row) * 128 + kh * 64);
        float nzp = 0.f;
#pragma unroll
        for (int g = 0; g < 8; ++g) {
            float4 v0 = Zr[2 * g], v1 = Zr[2 * g + 1];
            nzp = fmaf(v0.x, v0.x, fmaf(v0.y, v0.y, fmaf(v0.z, v0.z, fmaf(v0.w, v0.w, nzp))));
            nzp = fmaf(v1.x, v1.x, fmaf(v1.y, v1.y, fmaf(v1.z, v1.z, fmaf(v1.w, v1.w, nzp))));
            uint32_t p1[4], p2[4], p3[4];
            split_pack(v0.x, v0.y, p1[0], p2[0], p3[0]);
            split_pack(v0.z, v0.w, p1[1], p2[1], p3[1]);
            split_pack(v1.x, v1.y, p1[2], p2[2], p3[2]);
            split_pack(v1.z, v1.w, p1[3], p2[3], p3[3]);
            uint32_t cu  = (uint32_t)(kh * 8 + g);
            uint32_t off = (uint32_t)row * 256u + (((cu ^ (uint32_t)(row & 7))) << 4);
            *(uint4*)(sb + off)             = make_uint4(p1[0], p1[1], p1[2], p1[3]);
            *(uint4*)(sb + A_LVL + off)     = make_uint4(p2[0], p2[1], p2[2], p2[3]);
            *(uint4*)(sb + 2 * A_LVL + off) = make_uint4(p3[0], p3[1], p3[2], p3[3]);
        }
        float tot = nzp + __shfl_xor_sync(0xffffffffu, nzp, 1);
        if (kh == 0) { nz_sm[row] = tot; rz_sm[row] = rsqrtf(tot); }
    }
    __syncthreads();

    // per-thread row constants (8 rows: 4 mfrags x 2 halves)
    float nz8[8], rz8[8];
#pragma unroll
    for (int i = 0; i < 4; ++i)
#pragma unroll
        for (int h = 0; h < 2; ++h) {
            int ml = wy * 64 + i * 16 + qrow + 8 * h;
            nz8[i * 2 + h] = nz_sm[ml];
            rz8[i * 2 + h] = rz_sm[ml];
        }

    float bd8[8]; int bi8[8];
#pragma unroll
    for (int i = 0; i < 8; ++i) { bd8[i] = 3.4e38f; bi8[i] = 0; }

#pragma unroll 1
    for (int t = 0; t < NCHUNK; ++t) {
        if (t == NCHUNK - 1) cp_wait<0>(); else cp_wait<1>();
        __syncthreads();
        const uint32_t Bb = sbase + B_OFF + (uint32_t)(t & 1) * B_BUF;

        float acc[4][2][4];
#pragma unroll
        for (int i = 0; i < 4; ++i)
#pragma unroll
            for (int nf = 0; nf < 2; ++nf)
#pragma unroll
                for (int q = 0; q < 4; ++q) acc[i][nf][q] = 0.f;

        // 6-product split GEMM: A level sA reused across its B levels
#pragma unroll
        for (int sA = 0; sA < 3; ++sA) {
#pragma unroll
            for (int kk = 0; kk < 8; ++kk) {
                const int sel  = lane >> 3;
                const uint32_t cu = (uint32_t)(kk * 2 + (sel >> 1));
                uint32_t a[4][4];
#pragma unroll
                for (int i = 0; i < 4; ++i) {
                    int r = wy * 64 + i * 16 + (sel & 1) * 8 + (lane & 7);
                    uint32_t addr = sbase + sA * A_LVL + (uint32_t)r * 256u
                                  + (((cu ^ (uint32_t)(r & 7))) << 4);
                    ldsm_x4(a[i][0], a[i][1], a[i][2], a[i][3], addr);
                }
#pragma unroll
                for (int sB = 0; sB < 3 - sA; ++sB) {
                    int r = wx * 16 + (sel & 1) * 8 + (lane & 7);
                    uint32_t addr = Bb + sB * B_LVL + (uint32_t)r * 256u
                                  + (((cu ^ (uint32_t)(r & 7))) << 4);
                    uint32_t b0, b1, b2, b3;
                    ldsm_x4(b0, b1, b2, b3, addr);
                    uint32_t bf0[2] = { b0, b2 };
                    uint32_t bf1[2] = { b1, b3 };
#pragma unroll
                    for (int i = 0; i < 4; ++i) {
                        mma_bf16(acc[i][0], a[i], bf0);
                        mma_bf16(acc[i][1], a[i], bf1);
                    }
                }
            }
        }
        __syncthreads();                      // all warps done reading buf (t&1)
        if (t + 2 < NCHUNK) {                 // refill it with chunk t+2
            load_B(sbase + B_OFF + (uint32_t)(t & 1) * B_BUF, (t + 2) * BN, tid);
            cp_commit();
        }

        // ---- epilogue: dist/argmin + similarity (register-resident) ----
        const int nbase = t * BN + wx * 16;
#pragma unroll
        for (int nf = 0; nf < 2; ++nf) {
            const int nc = nbase + nf * 8 + qcol * 2;
            float2 ne2 = *reinterpret_cast<const float2*>(ne_sm + nc);
            float2 re2 = *reinterpret_cast<const float2*>(re_sm + nc);
#pragma unroll
            for (int i = 0; i < 4; ++i) {
#pragma unroll
                for (int h = 0; h < 2; ++h) {
                    const int idx = i * 2 + h;
                    const float d0 = acc[i][nf][h * 2 + 0];
                    const float d1 = acc[i][nf][h * 2 + 1];
                    // reference association order: (-2*dot + nz) + ne
                    float dd0 = fmaf(-2.f, d0, nz8[idx]) + ne2.x;
                    float dd1 = fmaf(-2.f, d1, nz8[idx]) + ne2.y;
                    if (dd0 < bd8[idx]) { bd8[idx] = dd0; bi8[idx] = nc; }
                    if (dd1 < bd8[idx]) { bd8[idx] = dd1; bi8[idx] = nc + 1; }
                    const int ml = wy * 64 + i * 16 + qrow + 8 * h;
                    float2 sv = make_float2(d0 * rz8[idx] * re2.x,
                                            d1 * rz8[idx] * re2.y);
                    *reinterpret_cast<float2*>(
                        sim + (size_t)(m0 + ml) * 1024 + nc) = sv;
                }
            }
        }
    }

    // ---- argmin reduction: lanes (cols) -> smem (n-warps) -> final ----
#pragma unroll
    for (int idx = 0; idx < 8; ++idx) {
        float bd = bd8[idx]; int bi = bi8[idx];
#pragma unroll
        for (int m = 1; m < 4; m <<= 1) {
            float od = __shfl_xor_sync(0xffffffffu, bd, m);
            int   oi = __shfl_xor_sync(0xffffffffu, bi, m);
            if (od < bd || (od == bd && oi < bi)) { bd = od; bi = oi; }
        }
        if (qcol == 0) {
            int i = idx >> 1, h = idx & 1;
            int ml = wy * 64 + i * 16 + qrow + 8 * h;
            redD[ml * 4 + wx] = bd;
            redI[ml * 4 + wx] = bi;
        }
    }
    __syncthreads();
    if (tid < 128) {
        float bd = redD[tid * 4]; int bi = redI[tid * 4];
#pragma unroll
        for (int w = 1; w < 4; ++w) {
            float od = redD[tid * 4 + w]; int oi = redI[tid * 4 + w];
            if (od < bd || (od == bd && oi < bi)) { bd = od; bi = oi; }
        }
        ids_sm[tid] = bi;
        idsf[m0 + tid] = (float)bi;
        lt_sm[tid] = sqrtf(fmaxf(bd, 0.f));   // ||z - z_q||^2 == dist_min exactly
    }
    __syncthreads();

    // z_q gather (codebook is L2-resident)
    const float4* E4  = reinterpret_cast<const float4*>(E);
    float4*       ZQ4 = reinterpret_cast<float4*>(zq);
#pragma unroll
    for (int rr = 0; rr < 16; ++rr) {
        int ml = warp * 16 + rr;
        int id = ids_sm[ml];
        ZQ4[(size_t)(m0 + ml) * 32 + lane] = E4[(size_t)id * 32 + lane];
    }

    // deterministic per-block loss partial (fixed serial order)
    if (tid == 0) {
        float s = 0.f;
        for (int i = 0; i < BM; ++i) s += lt_sm[i];
        g_partial[blockIdx.x] = s;
    }
}

// loss = 1.25 * mean ||z_e - z_q||  (deterministic tree)
__global__ void loss_final(float* __restrict__ out) {
    __shared__ float red[512];
    int tid = threadIdx.x;
    red[tid] = g_partial[tid];
    __syncthreads();
#pragma unroll
    for (int s = 256; s > 0; s >>= 1) {
        if (tid < s) red[tid] += red[tid + s];
        __syncthreads();
    }
    if (tid == 0) out[LOSS_OFF] = 1.25f * (red[0] * (1.f / 65536.f));
}

extern "C" void kernel_launch(void* const* d_in, const int* in_sizes, int n_in,
                              void* d_out, int out_size) {
    (void)in_sizes; (void)n_in; (void)out_size;
    const float* Z = (const float*)d_in[0];   // z_e            [65536, 128]
    const float* E = (const float*)d_in[1];   // vecs_embedding [1024, 128]
    float* out = (float*)d_out;

    cudaFuncSetAttribute((const void*)vq_main,
                         cudaFuncAttributeMaxDynamicSharedMemorySize, SMEM_BYTES);

    prep_e<<<KCODE / 8, 256>>>(E);
    vq_main<<<GRID_MAIN, 256, SMEM_BYTES>>>(Z, E, out);
    loss_final<<<1, 512>>>(out);
}

// round 9
// speedup vs baseline: 2.3576x; 1.9497x over previous
#include <cuda_runtime.h>
#include <cuda_fp16.h>
#include <math.h>
#include <stdint.h>

// ---------------- problem constants ----------------
#define M_TOK   65536
#define KCODE   1024
#define BM      64            // tokens per CTA
#define BN      64            // codes per chunk
#define NCHUNK  16
#define GRID_MAIN 1024

// Output layout (floats): [z_q | similarity | ids | loss]
#define SIM_OFF   8388608ULL
#define IDSG_OFF  75497472ULL
#define LOSS_OFF  75563008ULL

// ---------------- smem layout (byte offsets) ----------------
#define A_LVL      16384          // one A level: 64 rows x 256B
#define B_OFF      32768          // A = 2 levels
#define B_BUF      32768          // one B buffer: 2 levels x 16384
#define B_LVL      16384
#define NE_OFF     98304
#define RE_OFF     102400
#define NZ_OFF     106496
#define RZ_OFF     106752
#define IDS_SM     107008
#define LT_SM      107264
#define RED_OFF    107520         // 1024B dist + 1024B idx
#define SMEM_BYTES 109568

// ---------------- device scratch ----------------
__device__ __align__(16) __half g_Eb[KCODE * 256];  // per row: [e1(128)|e2(128)]
__device__ float g_ne[KCODE];
__device__ float g_re[KCODE];
__device__ float g_partial[GRID_MAIN];

// ---------------- PTX helpers (baseline ISA only) ----------------
__device__ __forceinline__ uint32_t smem_u32(const void* p) {
    uint32_t a;
    asm("{ .reg .u64 t; cvta.to.shared.u64 t, %1; cvt.u32.u64 %0, t; }" : "=r"(a) : "l"(p));
    return a;
}
__device__ __forceinline__ void cp16(uint32_t saddr, const void* g) {
    asm volatile("cp.async.cg.shared.global [%0], [%1], 16;" :: "r"(saddr), "l"(g));
}
__device__ __forceinline__ void cp_commit() { asm volatile("cp.async.commit_group;" ::: "memory"); }
template <int N>
__device__ __forceinline__ void cp_wait() { asm volatile("cp.async.wait_group %0;" :: "n"(N) : "memory"); }

__device__ __forceinline__ void ldsm_x4(uint32_t& r0, uint32_t& r1, uint32_t& r2, uint32_t& r3,
                                        uint32_t addr) {
    asm volatile("ldmatrix.sync.aligned.m8n8.x4.shared.b16 {%0,%1,%2,%3}, [%4];"
                 : "=r"(r0), "=r"(r1), "=r"(r2), "=r"(r3) : "r"(addr));
}
__device__ __forceinline__ void mma_f16(float* c, const uint32_t* a, const uint32_t* b) {
    asm volatile("mma.sync.aligned.m16n8k16.row.col.f32.f16.f16.f32 "
                 "{%0,%1,%2,%3}, {%4,%5,%6,%7}, {%8,%9}, {%0,%1,%2,%3};"
                 : "+f"(c[0]), "+f"(c[1]), "+f"(c[2]), "+f"(c[3])
                 : "r"(a[0]), "r"(a[1]), "r"(a[2]), "r"(a[3]), "r"(b[0]), "r"(b[1]));
}

// ---------------- 2-level fp16 split of a float pair, packed b32 per level --
__device__ __forceinline__ void split_pack(float a, float b, uint32_t& o1, uint32_t& o2) {
    __half a1 = __float2half_rn(a);
    __half a2 = __float2half_rn(a - __half2float(a1));
    __half b1 = __float2half_rn(b);
    __half b2 = __float2half_rn(b - __half2float(b1));
    __half2 p1 = __halves2half2(a1, b1);
    __half2 p2 = __halves2half2(a2, b2);
    o1 = *reinterpret_cast<uint32_t*>(&p1);
    o2 = *reinterpret_cast<uint32_t*>(&p2);
}

// ---------------- codebook prep: split + norms (warp per row) ---------------
__global__ void prep_e(const float* __restrict__ E) {
    int row  = blockIdx.x * 8 + (threadIdx.x >> 5);
    int lane = threadIdx.x & 31;
    float4 v = reinterpret_cast<const float4*>(E)[(size_t)row * 32 + lane];
    float s = fmaf(v.x, v.x, fmaf(v.y, v.y, fmaf(v.z, v.z, v.w * v.w)));
#pragma unroll
    for (int m = 16; m; m >>= 1) s += __shfl_xor_sync(0xffffffffu, s, m);
    if (lane == 0) { g_ne[row] = s; g_re[row] = rsqrtf(s); }
    uint32_t u1a, u2a, u1b, u2b;
    split_pack(v.x, v.y, u1a, u2a);
    split_pack(v.z, v.w, u1b, u2b);
    uint32_t* dst = reinterpret_cast<uint32_t*>(g_Eb + (size_t)row * 256);
    dst[lane * 2]      = u1a;  dst[lane * 2 + 1]      = u1b;   // level 1
    dst[64 + lane * 2] = u2a;  dst[64 + lane * 2 + 1] = u2b;   // level 2
}

// ---------------- B chunk loader: 64 codes x 2 levels = 32KB -----------------
__device__ __forceinline__ void load_B(uint32_t sbuf, int nb, int tid) {
#pragma unroll
    for (int i = 0; i < 8; ++i) {
        int idx = tid + 256 * i;          // 0..2047
        int lvl = idx >> 10;
        int rem = idx & 1023;
        int r   = rem >> 4;               // local code 0..63
        int j   = rem & 15;               // 16B column unit
        cp16(sbuf + lvl * B_LVL + (uint32_t)r * 256u
                  + (((uint32_t)(j ^ (r & 7))) << 4),
             g_Eb + (size_t)(nb + r) * 256 + lvl * 128 + j * 8);
    }
}

// ---------------- main fused kernel ----------------
__global__ __launch_bounds__(256, 2)
void vq_main(const float* __restrict__ Z, const float* __restrict__ E,
             float* __restrict__ out) {
    extern __shared__ char sb[];
    const uint32_t sbase = smem_u32(sb);

    const int tid  = threadIdx.x;
    const int lane = tid & 31;
    const int warp = tid >> 5;
    const int wy   = warp >> 2;      // m half (0,1): 32 rows each
    const int wx   = warp & 3;       // n quarter (0..3): 16 codes each
    const int qrow = lane >> 2;
    const int qcol = lane & 3;
    const int m0   = blockIdx.x * BM;

    float* ne_sm = (float*)(sb + NE_OFF);
    float* re_sm = (float*)(sb + RE_OFF);
    float* nz_sm = (float*)(sb + NZ_OFF);
    float* rz_sm = (float*)(sb + RZ_OFF);
    int*   ids_sm = (int*)(sb + IDS_SM);
    float* lt_sm  = (float*)(sb + LT_SM);
    float* redD   = (float*)(sb + RED_OFF);
    int*   redI   = (int*)(sb + RED_OFF + 1024);

    float* zq   = out;
    float* sim  = out + SIM_OFF;
    float* idsf = out + IDSG_OFF;

    // kick off B chunks 0,1 (independent of A prologue)
    load_B(sbase + B_OFF, 0, tid);          cp_commit();
    load_B(sbase + B_OFF + B_BUF, 64, tid); cp_commit();

    // codebook norms into smem
    for (int i = tid; i < KCODE; i += 256) { ne_sm[i] = g_ne[i]; re_sm[i] = g_re[i]; }

    // A prologue: thread = (row, k-quarter of 32 dims); fp32 norm + fp16 2-level split
    {
        const int row = tid >> 2, kh = tid & 3;
        const float4* Zr = reinterpret_cast<const float4*>(
            Z + (size_t)(m0 + row) * 128 + kh * 32);
        float nzp = 0.f;
        uint32_t p1[16], p2[16];
#pragma unroll
        for (int g = 0; g < 4; ++g) {
            float4 v0 = Zr[2 * g], v1 = Zr[2 * g + 1];
            nzp = fmaf(v0.x, v0.x, fmaf(v0.y, v0.y, fmaf(v0.z, v0.z, fmaf(v0.w, v0.w, nzp))));
            nzp = fmaf(v1.x, v1.x, fmaf(v1.y, v1.y, fmaf(v1.z, v1.z, fmaf(v1.w, v1.w, nzp))));
            split_pack(v0.x, v0.y, p1[4 * g + 0], p2[4 * g + 0]);
            split_pack(v0.z, v0.w, p1[4 * g + 1], p2[4 * g + 1]);
            split_pack(v1.x, v1.y, p1[4 * g + 2], p2[4 * g + 2]);
            split_pack(v1.z, v1.w, p1[4 * g + 3], p2[4 * g + 3]);
        }
#pragma unroll
        for (int q = 0; q < 4; ++q) {
            uint32_t u   = (uint32_t)(kh * 4 + q);
            uint32_t off = (uint32_t)row * 256u + (((u ^ (uint32_t)(row & 7))) << 4);
            *(uint4*)(sb + off)         = make_uint4(p1[4*q], p1[4*q+1], p1[4*q+2], p1[4*q+3]);
            *(uint4*)(sb + A_LVL + off) = make_uint4(p2[4*q], p2[4*q+1], p2[4*q+2], p2[4*q+3]);
        }
        nzp += __shfl_xor_sync(0xffffffffu, nzp, 1);
        nzp += __shfl_xor_sync(0xffffffffu, nzp, 2);
        if (kh == 0) { nz_sm[row] = nzp; rz_sm[row] = rsqrtf(nzp); }
    }
    __syncthreads();

    // per-thread row constants (4 rows: 2 mfrags x 2 halves)
    float nz4[4], rz4[4];
#pragma unroll
    for (int i = 0; i < 2; ++i)
#pragma unroll
        for (int h = 0; h < 2; ++h) {
            int ml = wy * 32 + i * 16 + qrow + 8 * h;
            nz4[i * 2 + h] = nz_sm[ml];
            rz4[i * 2 + h] = rz_sm[ml];
        }

    float bd4[4]; int bi4[4];
#pragma unroll
    for (int i = 0; i < 4; ++i) { bd4[i] = 3.4e38f; bi4[i] = 0; }

    const int sel = lane >> 3;          // 0..3 (ldmatrix address group)

#pragma unroll 1
    for (int t = 0; t < NCHUNK; ++t) {
        if (t == NCHUNK - 1) cp_wait<0>(); else cp_wait<1>();
        __syncthreads();
        const uint32_t Bb = sbase + B_OFF + (uint32_t)(t & 1) * B_BUF;

        float acc[2][2][4];
#pragma unroll
        for (int i = 0; i < 2; ++i)
#pragma unroll
            for (int nf = 0; nf < 2; ++nf)
#pragma unroll
                for (int q = 0; q < 4; ++q) acc[i][nf][q] = 0.f;

        // 3-product fp16 split GEMM: z1(e1,e2), z2(e1). A level reused over B levels.
#pragma unroll
        for (int sA = 0; sA < 2; ++sA) {
#pragma unroll
            for (int kk = 0; kk < 8; ++kk) {
                const uint32_t cu = (uint32_t)(kk * 2 + (sel >> 1));
                uint32_t a[2][4];
#pragma unroll
                for (int i = 0; i < 2; ++i) {
                    int r = wy * 32 + i * 16 + (sel & 1) * 8 + (lane & 7);
                    uint32_t addr = sbase + sA * A_LVL + (uint32_t)r * 256u
                                  + (((cu ^ (uint32_t)(r & 7))) << 4);
                    ldsm_x4(a[i][0], a[i][1], a[i][2], a[i][3], addr);
                }
#pragma unroll
                for (int sB = 0; sB < 2 - sA; ++sB) {
                    int r = wx * 16 + (sel & 1) * 8 + (lane & 7);
                    uint32_t addr = Bb + sB * B_LVL + (uint32_t)r * 256u
                                  + (((cu ^ (uint32_t)(r & 7))) << 4);
                    uint32_t b0, b1, b2, b3;
                    ldsm_x4(b0, b1, b2, b3, addr);
                    uint32_t bf0[2] = { b0, b2 };
                    uint32_t bf1[2] = { b1, b3 };
#pragma unroll
                    for (int i = 0; i < 2; ++i) {
                        mma_f16(acc[i][0], a[i], bf0);
                        mma_f16(acc[i][1], a[i], bf1);
                    }
                }
            }
        }
        __syncthreads();                      // all warps done reading buf (t&1)
        if (t + 2 < NCHUNK) {                 // refill it with chunk t+2
            load_B(sbase + B_OFF + (uint32_t)(t & 1) * B_BUF, (t + 2) * BN, tid);
            cp_commit();
        }

        // ---- epilogue: dist/argmin + similarity (register-resident) ----
        const int nbase = t * BN + wx * 16;
#pragma unroll
        for (int nf = 0; nf < 2; ++nf) {
            const int nc = nbase + nf * 8 + qcol * 2;
            float2 ne2 = *reinterpret_cast<const float2*>(ne_sm + nc);
            float2 re2 = *reinterpret_cast<const float2*>(re_sm + nc);
#pragma unroll
            for (int i = 0; i < 2; ++i) {
#pragma unroll
                for (int h = 0; h < 2; ++h) {
                    const int idx = i * 2 + h;
                    const float d0 = acc[i][nf][h * 2 + 0];
                    const float d1 = acc[i][nf][h * 2 + 1];
                    // reference association order: (-2*dot + nz) + ne
                    float dd0 = fmaf(-2.f, d0, nz4[idx]) + ne2.x;
                    float dd1 = fmaf(-2.f, d1, nz4[idx]) + ne2.y;
                    if (dd0 < bd4[idx]) { bd4[idx] = dd0; bi4[idx] = nc; }
                    if (dd1 < bd4[idx]) { bd4[idx] = dd1; bi4[idx] = nc + 1; }
                    const int ml = wy * 32 + i * 16 + qrow + 8 * h;
                    float2 sv = make_float2(d0 * rz4[idx] * re2.x,
                                            d1 * rz4[idx] * re2.y);
                    *reinterpret_cast<float2*>(
                        sim + (size_t)(m0 + ml) * 1024 + nc) = sv;
                }
            }
        }
    }

    // ---- argmin reduction: lanes (cols) -> smem (n-warps) -> final ----
#pragma unroll
    for (int idx = 0; idx < 4; ++idx) {
        float bd = bd4[idx]; int bi = bi4[idx];
#pragma unroll
        for (int m = 1; m < 4; m <<= 1) {
            float od = __shfl_xor_sync(0xffffffffu, bd, m);
            int   oi = __shfl_xor_sync(0xffffffffu, bi, m);
            if (od < bd || (od == bd && oi < bi)) { bd = od; bi = oi; }
        }
        if (qcol == 0) {
            int i = idx >> 1, h = idx & 1;
            int ml = wy * 32 + i * 16 + qrow + 8 * h;
            redD[ml * 4 + wx] = bd;
            redI[ml * 4 + wx] = bi;
        }
    }
    __syncthreads();
    if (tid < BM) {
        float bd = redD[tid * 4]; int bi = redI[tid * 4];
#pragma unroll
        for (int w = 1; w < 4; ++w) {
            float od = redD[tid * 4 + w]; int oi = redI[tid * 4 + w];
            if (od < bd || (od == bd && oi < bi)) { bd = od; bi = oi; }
        }
        ids_sm[tid] = bi;
        idsf[m0 + tid] = (float)bi;
        lt_sm[tid] = sqrtf(fmaxf(bd, 0.f));   // ||z - z_q||^2 == dist_min exactly
    }
    __syncthreads();

    // z_q gather (codebook is L2-resident)
    const float4* E4  = reinterpret_cast<const float4*>(E);
    float4*       ZQ4 = reinterpret_cast<float4*>(zq);
#pragma unroll
    for (int rr = 0; rr < 8; ++rr) {
        int ml = warp * 8 + rr;
        int id = ids_sm[ml];
        ZQ4[(size_t)(m0 + ml) * 32 + lane] = E4[(size_t)id * 32 + lane];
    }

    // deterministic per-block loss partial (fixed serial order)
    if (tid == 0) {
        float s = 0.f;
        for (int i = 0; i < BM; ++i) s += lt_sm[i];
        g_partial[blockIdx.x] = s;
    }
}

// loss = 1.25 * mean ||z_e - z_q||  (deterministic tree)
__global__ void loss_final(float* __restrict__ out) {
    __shared__ float red[1024];
    int tid = threadIdx.x;
    red[tid] = g_partial[tid];
    __syncthreads();
#pragma unroll
    for (int s = 512; s > 0; s >>= 1) {
        if (tid < s) red[tid] += red[tid + s];
        __syncthreads();
    }
    if (tid == 0) out[LOSS_OFF] = 1.25f * (red[0] * (1.f / 65536.f));
}

extern "C" void kernel_launch(void* const* d_in, const int* in_sizes, int n_in,
                              void* d_out, int out_size) {
    (void)in_sizes; (void)n_in; (void)out_size;
    const float* Z = (const float*)d_in[0];   // z_e            [65536, 128]
    const float* E = (const float*)d_in[1];   // vecs_embedding [1024, 128]
    float* out = (float*)d_out;

    cudaFuncSetAttribute((const void*)vq_main,
                         cudaFuncAttributeMaxDynamicSharedMemorySize, SMEM_BYTES);

    prep_e<<<KCODE / 8, 256>>>(E);
    vq_main<<<GRID_MAIN, 256, SMEM_BYTES>>>(Z, E, out);
    loss_final<<<1, 1024>>>(out);
}

// round 10
// speedup vs baseline: 2.4752x; 1.0499x over previous
#include <cuda_runtime.h>
#include <cuda_fp16.h>
#include <math.h>
#include <stdint.h>

// ---------------- problem constants ----------------
#define M_TOK   65536
#define KCODE   1024
#define BM      64            // tokens per CTA
#define BN      64            // codes per chunk
#define NCHUNK  16
#define GRID_MAIN 1024
#define MARGIN  0.09f         // ~16 sigma of fp16 pairwise dist-error

// Output layout (floats): [z_q | similarity | ids | loss]
#define SIM_OFF   8388608ULL
#define IDSG_OFF  75497472ULL
#define LOSS_OFF  75563008ULL

// ---------------- smem layout (byte offsets) ----------------
#define A_OFF      0              // z1 fp16: 64 rows x 256B = 16384
#define B_OFF      16384          // two B buffers x 16384
#define B_BUF      16384
#define ZF_OFF     16384          // fp32 Z tile reload (32KB, overlays B bufs post-loop)
#define NE_OFF     49152          // 4096
#define RE_OFF     53248          // 4096
#define NZ_OFF     57344          // 256
#define RZ_OFF     57600          // 256
#define REDD_OFF   57856          // 64 tok x 32 cand dists = 8192
#define REDI_OFF   66048          // 64 tok x 32 cand idx   = 8192
#define IDS_SM     74240          // 256
#define LT_SM      74496          // 256
#define SMEM_BYTES 74752

// ---------------- device scratch ----------------
__device__ __align__(16) __half g_Eh[KCODE * 128];  // fp16 codebook (level-1 only)
__device__ float g_ne[KCODE];
__device__ float g_re[KCODE];
__device__ float g_partial[GRID_MAIN];

// ---------------- PTX helpers (baseline ISA only) ----------------
__device__ __forceinline__ uint32_t smem_u32(const void* p) {
    uint32_t a;
    asm("{ .reg .u64 t; cvta.to.shared.u64 t, %1; cvt.u32.u64 %0, t; }" : "=r"(a) : "l"(p));
    return a;
}
__device__ __forceinline__ void cp16(uint32_t saddr, const void* g) {
    asm volatile("cp.async.cg.shared.global [%0], [%1], 16;" :: "r"(saddr), "l"(g));
}
__device__ __forceinline__ void cp_commit() { asm volatile("cp.async.commit_group;" ::: "memory"); }
template <int N>
__device__ __forceinline__ void cp_wait() { asm volatile("cp.async.wait_group %0;" :: "n"(N) : "memory"); }

__device__ __forceinline__ void ldsm_x4(uint32_t& r0, uint32_t& r1, uint32_t& r2, uint32_t& r3,
                                        uint32_t addr) {
    asm volatile("ldmatrix.sync.aligned.m8n8.x4.shared.b16 {%0,%1,%2,%3}, [%4];"
                 : "=r"(r0), "=r"(r1), "=r"(r2), "=r"(r3) : "r"(addr));
}
__device__ __forceinline__ void mma_f16(float* c, const uint32_t* a, const uint32_t* b) {
    asm volatile("mma.sync.aligned.m16n8k16.row.col.f32.f16.f16.f32 "
                 "{%0,%1,%2,%3}, {%4,%5,%6,%7}, {%8,%9}, {%0,%1,%2,%3};"
                 : "+f"(c[0]), "+f"(c[1]), "+f"(c[2]), "+f"(c[3])
                 : "r"(a[0]), "r"(a[1]), "r"(a[2]), "r"(a[3]), "r"(b[0]), "r"(b[1]));
}

// ---------------- codebook prep: fp16 convert + norms (warp per row) --------
__global__ void prep_e(const float* __restrict__ E) {
    int row  = blockIdx.x * 8 + (threadIdx.x >> 5);
    int lane = threadIdx.x & 31;
    float4 v = reinterpret_cast<const float4*>(E)[(size_t)row * 32 + lane];
    float s = fmaf(v.x, v.x, fmaf(v.y, v.y, fmaf(v.z, v.z, v.w * v.w)));
#pragma unroll
    for (int m = 16; m; m >>= 1) s += __shfl_xor_sync(0xffffffffu, s, m);
    if (lane == 0) { g_ne[row] = s; g_re[row] = rsqrtf(s); }
    __half2 h0 = __halves2half2(__float2half_rn(v.x), __float2half_rn(v.y));
    __half2 h1 = __halves2half2(__float2half_rn(v.z), __float2half_rn(v.w));
    uint32_t* dst = reinterpret_cast<uint32_t*>(g_Eh + (size_t)row * 128);
    dst[lane * 2]     = *reinterpret_cast<uint32_t*>(&h0);
    dst[lane * 2 + 1] = *reinterpret_cast<uint32_t*>(&h1);
}

// ---------------- B chunk loader: 64 codes x 128 fp16 = 16KB -----------------
__device__ __forceinline__ void load_B(uint32_t sbuf, int nb, int tid) {
#pragma unroll
    for (int i = 0; i < 4; ++i) {
        int idx = tid + 256 * i;          // 0..1023
        int r   = idx >> 4;               // local code 0..63
        int j   = idx & 15;               // 16B column unit
        cp16(sbuf + (uint32_t)r * 256u + (((uint32_t)(j ^ (r & 7))) << 4),
             g_Eh + (size_t)(nb + r) * 128 + j * 8);
    }
}

// ---------------- main fused kernel ----------------
__global__ __launch_bounds__(256, 2)
void vq_main(const float* __restrict__ Z, const float* __restrict__ E,
             float* __restrict__ out) {
    extern __shared__ char sb[];
    const uint32_t sbase = smem_u32(sb);

    const int tid  = threadIdx.x;
    const int lane = tid & 31;
    const int warp = tid >> 5;
    const int wy   = warp >> 2;      // m half (0,1): 32 rows each
    const int wx   = warp & 3;       // n quarter (0..3): 16 codes each
    const int qrow = lane >> 2;
    const int qcol = lane & 3;
    const int m0   = blockIdx.x * BM;

    float* ne_sm = (float*)(sb + NE_OFF);
    float* re_sm = (float*)(sb + RE_OFF);
    float* nz_sm = (float*)(sb + NZ_OFF);
    float* rz_sm = (float*)(sb + RZ_OFF);
    float* redD  = (float*)(sb + REDD_OFF);
    int*   redI  = (int*)(sb + REDI_OFF);
    int*   ids_sm = (int*)(sb + IDS_SM);
    float* lt_sm  = (float*)(sb + LT_SM);

    float* zq   = out;
    float* sim  = out + SIM_OFF;
    float* idsf = out + IDSG_OFF;

    // kick off B chunks 0,1
    load_B(sbase + B_OFF, 0, tid);          cp_commit();
    load_B(sbase + B_OFF + B_BUF, 64, tid); cp_commit();

    // codebook norms into smem
    for (int i = tid; i < KCODE; i += 256) { ne_sm[i] = g_ne[i]; re_sm[i] = g_re[i]; }

    // A prologue: thread = (row, k-quarter of 32 dims); fp32 norm + fp16 convert
    {
        const int row = tid >> 2, kh = tid & 3;
        const float4* Zr = reinterpret_cast<const float4*>(
            Z + (size_t)(m0 + row) * 128 + kh * 32);
        float nzp = 0.f;
        uint32_t p1[16];
#pragma unroll
        for (int g = 0; g < 4; ++g) {
            float4 v0 = Zr[2 * g], v1 = Zr[2 * g + 1];
            nzp = fmaf(v0.x, v0.x, fmaf(v0.y, v0.y, fmaf(v0.z, v0.z, fmaf(v0.w, v0.w, nzp))));
            nzp = fmaf(v1.x, v1.x, fmaf(v1.y, v1.y, fmaf(v1.z, v1.z, fmaf(v1.w, v1.w, nzp))));
            __half2 h0 = __halves2half2(__float2half_rn(v0.x), __float2half_rn(v0.y));
            __half2 h1 = __halves2half2(__float2half_rn(v0.z), __float2half_rn(v0.w));
            __half2 h2 = __halves2half2(__float2half_rn(v1.x), __float2half_rn(v1.y));
            __half2 h3 = __halves2half2(__float2half_rn(v1.z), __float2half_rn(v1.w));
            p1[4 * g + 0] = *reinterpret_cast<uint32_t*>(&h0);
            p1[4 * g + 1] = *reinterpret_cast<uint32_t*>(&h1);
            p1[4 * g + 2] = *reinterpret_cast<uint32_t*>(&h2);
            p1[4 * g + 3] = *reinterpret_cast<uint32_t*>(&h3);
        }
#pragma unroll
        for (int q = 0; q < 4; ++q) {
            uint32_t u   = (uint32_t)(kh * 4 + q);
            uint32_t off = (uint32_t)row * 256u + (((u ^ (uint32_t)(row & 7))) << 4);
            *(uint4*)(sb + A_OFF + off) = make_uint4(p1[4*q], p1[4*q+1], p1[4*q+2], p1[4*q+3]);
        }
        nzp += __shfl_xor_sync(0xffffffffu, nzp, 1);
        nzp += __shfl_xor_sync(0xffffffffu, nzp, 2);
        if (kh == 0) { nz_sm[row] = nzp; rz_sm[row] = rsqrtf(nzp); }
    }
    __syncthreads();

    // per-thread row constants (4 rows: 2 mfrags x 2 halves)
    float nz4[4], rz4[4];
#pragma unroll
    for (int i = 0; i < 2; ++i)
#pragma unroll
        for (int h = 0; h < 2; ++h) {
            int ml = wy * 32 + i * 16 + qrow + 8 * h;
            nz4[i * 2 + h] = nz_sm[ml];
            rz4[i * 2 + h] = rz_sm[ml];
        }

    // per-thread TOP-2 (dist, idx) per token row
    float bd1[4], bd2[4]; int bi1[4], bi2[4];
#pragma unroll
    for (int i = 0; i < 4; ++i) { bd1[i] = 3.4e38f; bd2[i] = 3.4e38f; bi1[i] = 0; bi2[i] = 0; }

    const int sel = lane >> 3;          // 0..3 (ldmatrix address group)

#pragma unroll 1
    for (int t = 0; t < NCHUNK; ++t) {
        if (t == NCHUNK - 1) cp_wait<0>(); else cp_wait<1>();
        __syncthreads();
        const uint32_t Bb = sbase + B_OFF + (uint32_t)(t & 1) * B_BUF;

        float acc[2][2][4];
#pragma unroll
        for (int i = 0; i < 2; ++i)
#pragma unroll
            for (int nf = 0; nf < 2; ++nf)
#pragma unroll
                for (int q = 0; q < 4; ++q) acc[i][nf][q] = 0.f;

        // single-product fp16 GEMM: z1 . e1
#pragma unroll
        for (int kk = 0; kk < 8; ++kk) {
            const uint32_t cu = (uint32_t)(kk * 2 + (sel >> 1));
            uint32_t a[2][4];
#pragma unroll
            for (int i = 0; i < 2; ++i) {
                int r = wy * 32 + i * 16 + (sel & 1) * 8 + (lane & 7);
                uint32_t addr = sbase + A_OFF + (uint32_t)r * 256u
                              + (((cu ^ (uint32_t)(r & 7))) << 4);
                ldsm_x4(a[i][0], a[i][1], a[i][2], a[i][3], addr);
            }
            int r = wx * 16 + (sel & 1) * 8 + (lane & 7);
            uint32_t addr = Bb + (uint32_t)r * 256u + (((cu ^ (uint32_t)(r & 7))) << 4);
            uint32_t b0, b1, b2, b3;
            ldsm_x4(b0, b1, b2, b3, addr);
            uint32_t bf0[2] = { b0, b2 };
            uint32_t bf1[2] = { b1, b3 };
#pragma unroll
            for (int i = 0; i < 2; ++i) {
                mma_f16(acc[i][0], a[i], bf0);
                mma_f16(acc[i][1], a[i], bf1);
            }
        }
        __syncthreads();                      // all warps done reading buf (t&1)
        if (t + 2 < NCHUNK) {                 // refill it with chunk t+2
            load_B(sbase + B_OFF + (uint32_t)(t & 1) * B_BUF, (t + 2) * BN, tid);
            cp_commit();
        }

        // ---- epilogue: approx dist -> top-2 tracking + similarity stores ----
        const int nbase = t * BN + wx * 16;
#pragma unroll
        for (int nf = 0; nf < 2; ++nf) {
            const int nc = nbase + nf * 8 + qcol * 2;
            float2 ne2 = *reinterpret_cast<const float2*>(ne_sm + nc);
            float2 re2 = *reinterpret_cast<const float2*>(re_sm + nc);
#pragma unroll
            for (int i = 0; i < 2; ++i) {
#pragma unroll
                for (int h = 0; h < 2; ++h) {
                    const int idx = i * 2 + h;
                    const float d0 = acc[i][nf][h * 2 + 0];
                    const float d1 = acc[i][nf][h * 2 + 1];
                    float dd0 = fmaf(-2.f, d0, nz4[idx]) + ne2.x;
                    float dd1 = fmaf(-2.f, d1, nz4[idx]) + ne2.y;
                    // top-2 insert (codes arrive in increasing index order)
                    if (dd0 < bd2[idx]) {
                        if (dd0 < bd1[idx]) { bd2[idx]=bd1[idx]; bi2[idx]=bi1[idx];
                                              bd1[idx]=dd0; bi1[idx]=nc; }
                        else                { bd2[idx]=dd0; bi2[idx]=nc; }
                    }
                    if (dd1 < bd2[idx]) {
                        if (dd1 < bd1[idx]) { bd2[idx]=bd1[idx]; bi2[idx]=bi1[idx];
                                              bd1[idx]=dd1; bi1[idx]=nc + 1; }
                        else                { bd2[idx]=dd1; bi2[idx]=nc + 1; }
                    }
                    const int ml = wy * 32 + i * 16 + qrow + 8 * h;
                    float2 sv = make_float2(d0 * rz4[idx] * re2.x,
                                            d1 * rz4[idx] * re2.y);
                    *reinterpret_cast<float2*>(
                        sim + (size_t)(m0 + ml) * 1024 + nc) = sv;
                }
            }
        }
    }

    // ---- dump per-thread top-2 candidates (32 per token) ----
#pragma unroll
    for (int idx = 0; idx < 4; ++idx) {
        int i = idx >> 1, h = idx & 1;
        int tok = wy * 32 + i * 16 + qrow + 8 * h;
        int base = tok * 32 + (wx * 4 + qcol) * 2;
        redD[base] = bd1[idx];     redI[base] = bi1[idx];
        redD[base + 1] = bd2[idx]; redI[base + 1] = bi2[idx];
    }

    // ---- reload fp32 Z tile into smem (B buffers are dead now) ----
    {
        float4* zf = (float4*)(sb + ZF_OFF);
        const float4* Zg = reinterpret_cast<const float4*>(Z) + (size_t)m0 * 32;
#pragma unroll
        for (int i = 0; i < 8; ++i) zf[tid + 256 * i] = Zg[tid + 256 * i];
    }
    __syncthreads();

    // ---- exact fp32 refine: one thread per token ----
    if (tid < BM) {
        const int tok = tid;
        float m1 = 3.4e38f;
#pragma unroll
        for (int e = 0; e < 32; ++e) m1 = fminf(m1, redD[tok * 32 + e]);
        const float thr = m1 + MARGIN;
        const float nzt = nz_sm[tok];
        const float4* zf = (float4*)(sb + ZF_OFF) + tok * 32;
        float bestd = 3.4e38f; int besti = KCODE;
        for (int e = 0; e < 32; ++e) {
            if (redD[tok * 32 + e] <= thr) {
                const int id = redI[tok * 32 + e];
                const float4* Er = reinterpret_cast<const float4*>(E) + (size_t)id * 32;
                float dot = 0.f;
#pragma unroll
                for (int q = 0; q < 32; ++q) {
                    float4 a = zf[q], b = Er[q];
                    dot = fmaf(a.x, b.x, fmaf(a.y, b.y, fmaf(a.z, b.z, fmaf(a.w, b.w, dot))));
                }
                float de = fmaf(-2.f, dot, nzt) + ne_sm[id];   // reference association order
                if (de < bestd || (de == bestd && id < besti)) { bestd = de; besti = id; }
            }
        }
        ids_sm[tok] = besti;
        idsf[m0 + tok] = (float)besti;
        lt_sm[tok] = sqrtf(fmaxf(bestd, 0.f));   // ||z - z_q||^2 == dist_min exactly
    }
    __syncthreads();

    // z_q gather (codebook is L2-resident)
    const float4* E4  = reinterpret_cast<const float4*>(E);
    float4*       ZQ4 = reinterpret_cast<float4*>(zq);
#pragma unroll
    for (int rr = 0; rr < 8; ++rr) {
        int ml = warp * 8 + rr;
        int id = ids_sm[ml];
        ZQ4[(size_t)(m0 + ml) * 32 + lane] = E4[(size_t)id * 32 + lane];
    }

    // deterministic per-block loss partial (fixed serial order)
    if (tid == 0) {
        float s = 0.f;
        for (int i = 0; i < BM; ++i) s += lt_sm[i];
        g_partial[blockIdx.x] = s;
    }
}

// loss = 1.25 * mean ||z_e - z_q||  (deterministic tree)
__global__ void loss_final(float* __restrict__ out) {
    __shared__ float red[1024];
    int tid = threadIdx.x;
    red[tid] = g_partial[tid];
    __syncthreads();
#pragma unroll
    for (int s = 512; s > 0; s >>= 1) {
        if (tid < s) red[tid] += red[tid + s];
        __syncthreads();
    }
    if (tid == 0) out[LOSS_OFF] = 1.25f * (red[0] * (1.f / 65536.f));
}

extern "C" void kernel_launch(void* const* d_in, const int* in_sizes, int n_in,
                              void* d_out, int out_size) {
    (void)in_sizes; (void)n_in; (void)out_size;
    const float* Z = (const float*)d_in[0];   // z_e            [65536, 128]
    const float* E = (const float*)d_in[1];   // vecs_embedding [1024, 128]
    float* out = (float*)d_out;

    cudaFuncSetAttribute((const void*)vq_main,
                         cudaFuncAttributeMaxDynamicSharedMemorySize, SMEM_BYTES);

    prep_e<<<KCODE / 8, 256>>>(E);
    vq_main<<<GRID_MAIN, 256, SMEM_BYTES>>>(Z, E, out);
    loss_final<<<1, 1024>>>(out);
}